// round 5
// baseline (speedup 1.0000x reference)
#include <cuda_runtime.h>
#include <cstdint>
#include <cstddef>

#define TT 2048
#define BB 32
#define HH 256
#define NCTA 64
#define NCELL (TT * 2)

// ---------------- global scratch (allocation-free) ------------------------------
__device__ float g_gi[(size_t)TT * BB * 3 * HH];   // x @ w_ih^T + b_ih  [T][B][768]
__device__ uint2 g_hp[2][HH * BB];                 // (value, seq) pairs, col-major [col][b]
__device__ unsigned g_base;                        // bumped by NCELL+2 each launch

// ---------------- primitives -----------------------------------------------------
__device__ __forceinline__ uint4 ldcg4(const uint4* p) {
  uint4 v;
  asm volatile("ld.global.cg.v4.u32 {%0,%1,%2,%3}, [%4];"
               : "=r"(v.x), "=r"(v.y), "=r"(v.z), "=r"(v.w) : "l"(p) : "memory");
  return v;
}
__device__ __forceinline__ void st64rel(void* p, uint64_t v) {
  asm volatile("st.relaxed.gpu.global.u64 [%0], %1;" :: "l"(p), "l"(v) : "memory");
}
__device__ __forceinline__ uint64_t pack2(float a, float b) {
  uint64_t r;
  asm("mov.b64 %0, {%1, %2};" : "=l"(r) : "f"(a), "f"(b));
  return r;
}
__device__ __forceinline__ void unpack2(float& a, float& b, uint64_t v) {
  asm("mov.b64 {%0, %1}, %2;" : "=f"(a), "=f"(b) : "l"(v));
}
__device__ __forceinline__ void fma2(uint64_t& d, uint64_t a, uint64_t b) {
  asm("fma.rn.f32x2 %0, %1, %2, %0;" : "+l"(d) : "l"(a), "l"(b));
}

// ---------------- per-launch seq-base bump ---------------------------------------
__global__ void bump_base_kernel() { g_base += (unsigned)(NCELL + 2); }

// ---------------- gi precompute: g_gi[t][b][g] = x_t[b]·w_ih[g] + b_ih[g] --------
__global__ __launch_bounds__(256) void gi_kernel(
    const float* __restrict__ x, const float* __restrict__ w_ih,
    const float* __restrict__ b_ih) {
  __shared__ float xs[32 * 260];
  __shared__ float ws[128 * 20];
  const int t   = blockIdx.x;
  const int gc0 = blockIdx.y * 128;
  const int tid = threadIdx.x;

  for (int i = tid; i < 2048; i += 256) {
    int b = i >> 6;
    int c4 = (i & 63) << 2;
    float4 v = *(const float4*)(x + ((size_t)b * TT + t) * HH + c4);
    *(float4*)(xs + b * 260 + c4) = v;
  }

  const int bq = tid >> 5;
  const int gq = tid & 31;

  float acc[4][4];
#pragma unroll
  for (int i = 0; i < 4; i++)
#pragma unroll
    for (int j = 0; j < 4; j++) acc[i][j] = 0.f;

  for (int kt = 0; kt < 16; ++kt) {
    const int k0 = kt * 16;
    __syncthreads();
    for (int i = tid; i < 512; i += 256) {
      int r = i >> 2;
      int c4 = (i & 3) << 2;
      *(float4*)(ws + r * 20 + c4) =
          *(const float4*)(w_ih + (size_t)(gc0 + r) * HH + k0 + c4);
    }
    __syncthreads();
#pragma unroll
    for (int q = 0; q < 4; ++q) {
      const int kk = q << 2;
      float4 wv[4];
#pragma unroll
      for (int j = 0; j < 4; j++)
        wv[j] = *(const float4*)(ws + (gq + 32 * j) * 20 + kk);
#pragma unroll
      for (int i = 0; i < 4; i++) {
        float4 xv = *(const float4*)(xs + (bq * 4 + i) * 260 + k0 + kk);
#pragma unroll
        for (int j = 0; j < 4; j++) {
          acc[i][j] += xv.x * wv[j].x + xv.y * wv[j].y +
                       xv.z * wv[j].z + xv.w * wv[j].w;
        }
      }
    }
  }
#pragma unroll
  for (int j = 0; j < 4; j++) {
    int g = gc0 + gq + 32 * j;
    float bias = b_ih[g];
#pragma unroll
    for (int i = 0; i < 4; i++) {
      int b = bq * 4 + i;
      g_gi[((size_t)t * BB + b) * 768 + g] = acc[i][j] + bias;
    }
  }
}

// ---------------- persistent recurrent scan (payload-seq sync, no fences) --------
__global__ __launch_bounds__(256, 1) void scan_kernel(
    const float* __restrict__ hidden, const float* __restrict__ w_hh,
    const float* __restrict__ b_hh, float* __restrict__ out) {
  extern __shared__ float sm[];
  float* hT   = sm;                  // [k*32 + b] values (32 KB)
  float* part = sm + HH * BB;        // 256 threads * 25 floats
  float* bhh  = part + 256 * 25;     // 12 floats
  __shared__ unsigned s_base;

  const int tid = threadIdx.x;
  const int c   = blockIdx.x;
  const int kh  = tid >> 4;          // K-slice [kh*16, kh*16+16)
  const int jj  = (tid >> 2) & 3;    // local column
  const int bt  = tid & 3;           // batch octet [bt*8, bt*8+8)

  if (tid == 0) s_base = g_base;

  // persistent weights in registers
  float wreg[3][16];
#pragma unroll
  for (int g = 0; g < 3; ++g) {
    const float* wrow = w_hh + (size_t)(g * HH + c * 4 + jj) * HH + kh * 16;
#pragma unroll
    for (int i4 = 0; i4 < 4; ++i4) {
      float4 v = *(const float4*)(wrow + i4 * 4);
      wreg[g][i4 * 4 + 0] = v.x;
      wreg[g][i4 * 4 + 1] = v.y;
      wreg[g][i4 * 4 + 2] = v.z;
      wreg[g][i4 * 4 + 3] = v.w;
    }
  }
  if (tid < 12) bhh[tid] = b_hh[(tid >> 2) * HH + c * 4 + (tid & 3)];
  __syncthreads();
  const unsigned base = s_base;

  float* myPart = part + tid * 25;
  const int eb = tid >> 2, ej = tid & 3;          // epilogue mapping (tid<128)
  const int eidx = (c * 4 + ej) * BB + eb;        // owned element, col-major

  for (int cell = 0; cell < NCELL; ++cell) {
    // ---- stage h into SMEM (self-validating payload polls) ----
    if (cell == 0) {
      for (int i = tid; i < HH * BB; i += 256)
        hT[i] = hidden[((i & 31) << 8) + (i >> 5)];   // hT[col*32+b] = hidden[b][col]
    } else {
      const uint4* src = (const uint4*)(g_hp[cell & 1]);
      const unsigned tgt = base + (unsigned)cell;
#pragma unroll
      for (int rr = 0; rr < 2; ++rr) {
        uint4 v[8];
#pragma unroll
        for (int q = 0; q < 8; ++q)
          v[q] = ldcg4(src + tid + (rr * 8 + q) * 256);
#pragma unroll
        for (int q = 0; q < 8; ++q) {
          while (v[q].y != tgt || v[q].w != tgt) {
            __nanosleep(40);
            v[q] = ldcg4(src + tid + (rr * 8 + q) * 256);
          }
        }
#pragma unroll
        for (int q = 0; q < 8; ++q) {
          const int idx = tid + (rr * 8 + q) * 256;
          ((float2*)hT)[idx] =
              make_float2(__uint_as_float(v[q].x), __uint_as_float(v[q].z));
        }
      }
    }
    // prefetch gi for epilogue threads
    float gir = 0.f, giz = 0.f, gin = 0.f;
    if (tid < 128) {
      const float* gp = g_gi + (size_t)(cell >> 1) * BB * 768 + eb * 768 + c * 4 + ej;
      gir = gp[0];
      giz = gp[256];
      gin = gp[512];
    }
    __syncthreads();

    // hold value for epilogue (read while hT is stable)
    float hold = 0.f;
    if (tid < 128) hold = hT[(c * 4 + ej) * 32 + eb];

    // ---- partial gh with packed f32x2 FMA; weights from registers ----
    uint64_t acc[3][4];
#pragma unroll
    for (int g = 0; g < 3; ++g)
#pragma unroll
      for (int p = 0; p < 4; ++p) acc[g][p] = pack2(0.f, 0.f);

#pragma unroll
    for (int i = 0; i < 16; ++i) {
      const int k = kh * 16 + i;
      const float* hp = hT + k * 32 + bt * 8;
      const float4 ha = *(const float4*)hp;
      const float4 hb = *(const float4*)(hp + 4);
      const uint64_t h01 = pack2(ha.x, ha.y);
      const uint64_t h23 = pack2(ha.z, ha.w);
      const uint64_t h45 = pack2(hb.x, hb.y);
      const uint64_t h67 = pack2(hb.z, hb.w);
#pragma unroll
      for (int g = 0; g < 3; ++g) {
        const uint64_t w2 = pack2(wreg[g][i], wreg[g][i]);
        fma2(acc[g][0], w2, h01);
        fma2(acc[g][1], w2, h23);
        fma2(acc[g][2], w2, h45);
        fma2(acc[g][3], w2, h67);
      }
    }
#pragma unroll
    for (int g = 0; g < 3; ++g)
#pragma unroll
      for (int p = 0; p < 4; ++p) {
        float a, b;
        unpack2(a, b, acc[g][p]);
        myPart[(p * 2 + 0) * 3 + g] = a;
        myPart[(p * 2 + 1) * 3 + g] = b;
      }
    __syncthreads();

    // ---- epilogue (tid<128): reduce, gates, publish value+seq in one STG.64 ----
    if (tid < 128) {
      const int bt2 = eb >> 3, bl = eb & 7;
      float sr = bhh[ej], sz = bhh[4 + ej], sn = bhh[8 + ej];
#pragma unroll
      for (int k2 = 0; k2 < 16; ++k2) {
        const float* p = part + (k2 * 16 + ej * 4 + bt2) * 25 + bl * 3;
        sr += p[0];
        sz += p[1];
        sn += p[2];
      }
      const float r = 1.f / (1.f + expf(-(gir + sr)));
      const float z = 1.f / (1.f + expf(-(giz + sz)));
      const float n = tanhf(gin + r * sn);
      const float hn = (1.f - z) * n + z * hold;
      const uint64_t pkd =
          ((uint64_t)(base + (unsigned)cell + 1u) << 32) | (uint64_t)__float_as_uint(hn);
      st64rel(&g_hp[(cell + 1) & 1][eidx], pkd);
      if (cell & 1)
        out[((size_t)(cell >> 1) * BB + eb) * HH + c * 4 + ej] = hn;
    }
    // no barrier: next staging self-synchronizes on payload seq;
    // hT/part hazards are covered by the two __syncthreads above.
  }
}

// ---------------- launch ---------------------------------------------------------
extern "C" void kernel_launch(void* const* d_in, const int* in_sizes, int n_in,
                              void* d_out, int out_size) {
  const float *input = 0, *hidden = 0, *w_ih = 0, *w_hh = 0, *b_ih = 0, *b_hh = 0;
  for (int i = 0; i < n_in; ++i) {
    long s = in_sizes[i];
    if (s == (long)BB * TT * HH) {
      input = (const float*)d_in[i];
    } else if (s == BB * HH && !hidden) {
      hidden = (const float*)d_in[i];
    } else if (s == 3 * HH * HH) {
      if (!w_ih) w_ih = (const float*)d_in[i]; else w_hh = (const float*)d_in[i];
    } else if (s == 3 * HH) {
      if (!b_ih) b_ih = (const float*)d_in[i]; else b_hh = (const float*)d_in[i];
    }
  }
  static int smem_set = 0;
  const int smem_bytes = (HH * BB + 256 * 25 + 16) * (int)sizeof(float);
  if (!smem_set) {
    cudaFuncSetAttribute(scan_kernel, cudaFuncAttributeMaxDynamicSharedMemorySize,
                         smem_bytes);
    smem_set = 1;
  }
  bump_base_kernel<<<1, 1>>>();
  gi_kernel<<<dim3(TT, 6), 256>>>(input, w_ih, b_ih);
  scan_kernel<<<NCTA, 256, smem_bytes>>>(hidden, w_hh, b_hh, (float*)d_out);
}

// round 6
// speedup vs baseline: 1.5505x; 1.5505x over previous
#include <cuda_runtime.h>
#include <cstdint>
#include <cstddef>

#define TT 2048
#define BB 32
#define HH 256
#define NCTA 64
#define NCELL (TT * 2)

// ---------------- global scratch (allocation-free) ------------------------------
__device__ float g_gi[(size_t)TT * BB * 3 * HH];   // x @ w_ih^T + b_ih  [T][B][768]
__device__ float g_h[2][HH * BB];                  // col-major [col][b], double buffered
__device__ unsigned g_ctr;                         // arrival counter (zeroed per launch)

// ---------------- sync primitives ------------------------------------------------
__device__ __forceinline__ unsigned ld_acq(const unsigned* p) {
  unsigned v;
  asm volatile("ld.acquire.gpu.global.u32 %0, [%1];" : "=r"(v) : "l"(p) : "memory");
  return v;
}
__device__ __forceinline__ void red_release(unsigned* p, unsigned v) {
  asm volatile("red.release.gpu.global.add.u32 [%0], %1;" :: "l"(p), "r"(v) : "memory");
}
__device__ __forceinline__ float4 ldcg4f(const float4* p) {
  float4 v;
  asm volatile("ld.global.cg.v4.f32 {%0,%1,%2,%3}, [%4];"
               : "=f"(v.x), "=f"(v.y), "=f"(v.z), "=f"(v.w) : "l"(p) : "memory");
  return v;
}

// ---------------- packed f32x2 helpers --------------------------------------------
__device__ __forceinline__ uint64_t pack2(float a, float b) {
  uint64_t r;
  asm("mov.b64 %0, {%1, %2};" : "=l"(r) : "f"(a), "f"(b));
  return r;
}
__device__ __forceinline__ void unpack2(float& a, float& b, uint64_t v) {
  asm("mov.b64 {%0, %1}, %2;" : "=f"(a), "=f"(b) : "l"(v));
}
__device__ __forceinline__ void fma2(uint64_t& d, uint64_t a, uint64_t b) {
  asm("fma.rn.f32x2 %0, %1, %2, %0;" : "+l"(d) : "l"(a), "l"(b));
}

// ---------------- per-launch counter reset ----------------------------------------
__global__ void zero_ctr_kernel() { g_ctr = 0u; }

// ---------------- gi precompute (f32x2 packed over k-pairs) -----------------------
__global__ __launch_bounds__(256) void gi_kernel(
    const float* __restrict__ x, const float* __restrict__ w_ih,
    const float* __restrict__ b_ih) {
  __shared__ float xs[32 * 260];      // x_t, [b][k], stride 260
  __shared__ float ws[128 * 18];      // w tile, 128 rows x 16 k, stride 18 (8B aligned)
  const int t   = blockIdx.x;
  const int gc0 = blockIdx.y * 128;
  const int tid = threadIdx.x;

  for (int i = tid; i < 2048; i += 256) {
    int b = i >> 6;
    int c4 = (i & 63) << 2;
    float4 v = *(const float4*)(x + ((size_t)b * TT + t) * HH + c4);
    *(float4*)(xs + b * 260 + c4) = v;
  }

  const int bq = tid >> 5;   // warp -> batches bq*4..+4
  const int gq = tid & 31;   // rows gq + 32*j

  uint64_t acc2[4][4];       // packed (k-even, k-odd) partial sums
#pragma unroll
  for (int i = 0; i < 4; i++)
#pragma unroll
    for (int j = 0; j < 4; j++) acc2[i][j] = pack2(0.f, 0.f);

  for (int kt = 0; kt < 16; ++kt) {
    const int k0 = kt * 16;
    __syncthreads();
    for (int i = tid; i < 1024; i += 256) {   // 128 rows x 8 float2
      int r = i >> 3;
      int c2 = (i & 7) << 1;
      *(float2*)(ws + r * 18 + c2) =
          *(const float2*)(w_ih + (size_t)(gc0 + r) * HH + k0 + c2);
    }
    __syncthreads();
#pragma unroll
    for (int kp = 0; kp < 8; ++kp) {
      const int kk = kp << 1;
      uint64_t w2[4];
#pragma unroll
      for (int j = 0; j < 4; j++)
        w2[j] = *(const uint64_t*)(ws + (gq + 32 * j) * 18 + kk);
#pragma unroll
      for (int i = 0; i < 4; i++) {
        const uint64_t x2 = *(const uint64_t*)(xs + (bq * 4 + i) * 260 + k0 + kk);
#pragma unroll
        for (int j = 0; j < 4; j++) fma2(acc2[i][j], x2, w2[j]);
      }
    }
  }
#pragma unroll
  for (int j = 0; j < 4; j++) {
    int g = gc0 + gq + 32 * j;
    float bias = b_ih[g];
#pragma unroll
    for (int i = 0; i < 4; i++) {
      float a, b;
      unpack2(a, b, acc2[i][j]);
      g_gi[((size_t)t * BB + (bq * 4 + i)) * 768 + g] = a + b + bias;
    }
  }
}

// ---------------- persistent recurrent scan ---------------------------------------
// 64 CTAs; CTA c owns h columns c*4..c*4+3; 12 w_hh rows in registers.
// Sync: red.release arrival per CTA; one poller thread; SMEM "go" broadcast.
// Per-warp hT staging (own 32 rows), double-buffered partials, register hold.
__global__ __launch_bounds__(256, 1) void scan_kernel(
    const float* __restrict__ hidden, const float* __restrict__ w_hh,
    const float* __restrict__ b_hh, float* __restrict__ out) {
  extern __shared__ float sm[];
  float* hT    = sm;                 // 8192 floats  [k*32+b]
  float* part0 = sm + 8192;          // 6400
  float* part1 = part0 + 6400;       // 6400
  float* bhh   = part1 + 6400;       // 12
  __shared__ volatile unsigned s_go;

  const int tid  = threadIdx.x;
  const int c    = blockIdx.x;
  const int w    = tid >> 5;
  const int lane = tid & 31;
  const int kh   = tid >> 4;         // K-slice [kh*16, kh*16+16)
  const int jj   = (tid >> 2) & 3;   // local column
  const int bt   = tid & 3;          // batch octet

  if (tid == 0) s_go = 0u;

  // persistent weights in registers
  float wreg[3][16];
#pragma unroll
  for (int g = 0; g < 3; ++g) {
    const float* wrow = w_hh + (size_t)(g * HH + c * 4 + jj) * HH + kh * 16;
#pragma unroll
    for (int i4 = 0; i4 < 4; ++i4) {
      float4 v = *(const float4*)(wrow + i4 * 4);
      wreg[g][i4 * 4 + 0] = v.x;
      wreg[g][i4 * 4 + 1] = v.y;
      wreg[g][i4 * 4 + 2] = v.z;
      wreg[g][i4 * 4 + 3] = v.w;
    }
  }
  if (tid < 12) bhh[tid] = b_hh[(tid >> 2) * HH + c * 4 + (tid & 3)];

  const int eb = tid >> 2, ej = tid & 3;         // epilogue mapping (tid<128)
  const int eidx = (c * 4 + ej) * BB + eb;       // owned element, col-major
  float hold = 0.f;
  if (tid < 128) hold = hidden[eb * HH + c * 4 + ej];
  __syncthreads();

  for (int cell = 0; cell < NCELL; ++cell) {
    // ---- wait for go, then stage own hT slice (per-warp, no CTA barrier) ----
    if (cell == 0) {
      for (int i = lane; i < 1024; i += 32) {
        int k = w * 32 + (i >> 5);
        int b = i & 31;
        hT[k * 32 + b] = hidden[b * HH + k];
      }
    } else {
      while (s_go < (unsigned)cell) {}
      asm volatile("fence.acq_rel.cta;" ::: "memory");
      const float4* src = (const float4*)(g_h[cell & 1]) + w * 256;
      float4* dst = (float4*)hT + w * 256;
#pragma unroll
      for (int q = 0; q < 8; ++q)
        dst[lane + q * 32] = ldcg4f(src + lane + q * 32);
    }
    __syncwarp();
    // gi prefetch for epilogue threads (latency hidden behind compute)
    float gir = 0.f, giz = 0.f, gin = 0.f;
    if (tid < 128) {
      const float* gp = g_gi + (size_t)(cell >> 1) * BB * 768 + eb * 768 + c * 4 + ej;
      gir = gp[0];
      giz = gp[256];
      gin = gp[512];
    }

    float* partBuf = (cell & 1) ? part1 : part0;

    // ---- partial gh with packed f32x2 FMA; weights from registers ----
    uint64_t acc[3][4];
#pragma unroll
    for (int g = 0; g < 3; ++g)
#pragma unroll
      for (int p = 0; p < 4; ++p) acc[g][p] = pack2(0.f, 0.f);

#pragma unroll
    for (int i = 0; i < 16; ++i) {
      const int k = kh * 16 + i;
      const float* hp = hT + k * 32 + bt * 8;
      const float4 ha = *(const float4*)hp;
      const float4 hb = *(const float4*)(hp + 4);
      const uint64_t h01 = pack2(ha.x, ha.y);
      const uint64_t h23 = pack2(ha.z, ha.w);
      const uint64_t h45 = pack2(hb.x, hb.y);
      const uint64_t h67 = pack2(hb.z, hb.w);
#pragma unroll
      for (int g = 0; g < 3; ++g) {
        const uint64_t w2 = pack2(wreg[g][i], wreg[g][i]);
        fma2(acc[g][0], w2, h01);
        fma2(acc[g][1], w2, h23);
        fma2(acc[g][2], w2, h45);
        fma2(acc[g][3], w2, h67);
      }
    }
    {
      float* myPart = partBuf + tid * 25;
#pragma unroll
      for (int g = 0; g < 3; ++g)
#pragma unroll
        for (int p = 0; p < 4; ++p) {
          float a, b;
          unpack2(a, b, acc[g][p]);
          myPart[(p * 2 + 0) * 3 + g] = a;
          myPart[(p * 2 + 1) * 3 + g] = b;
        }
    }
    __syncthreads();   // partials of this cell visible to epilogue

    // ---- epilogue (warps 0-3) ; poller (tid 255) overlapped ----
    if (tid < 128) {
      const int bt2 = eb >> 3, bl = eb & 7;
      float sr = bhh[ej], sz = bhh[4 + ej], sn = bhh[8 + ej];
#pragma unroll
      for (int k2 = 0; k2 < 16; ++k2) {
        const float* p = partBuf + (k2 * 16 + ej * 4 + bt2) * 25 + bl * 3;
        sr += p[0];
        sz += p[1];
        sn += p[2];
      }
      const float r = 1.f / (1.f + expf(-(gir + sr)));
      const float z = 1.f / (1.f + expf(-(giz + sz)));
      const float n = tanhf(gin + r * sn);
      const float hn = (1.f - z) * n + z * hold;
      hold = hn;                                      // register-carried for next cell
      g_h[(cell + 1) & 1][eidx] = hn;                 // publish
      asm volatile("bar.sync 1, 128;" ::: "memory");
      if (tid == 0) red_release(&g_ctr, 1u);          // release: orders the publishes
      if (cell & 1)                                   // out store off critical path
        out[((size_t)(cell >> 1) * BB + eb) * HH + c * 4 + ej] = hn;
    } else if (tid == 255 && cell + 1 < NCELL) {
      const unsigned tgt = 64u * (unsigned)(cell + 1);
      while ((int)(ld_acq(&g_ctr) - tgt) < 0) {}
      asm volatile("fence.acq_rel.cta;" ::: "memory");
      s_go = (unsigned)(cell + 1);
    }
    // no trailing barrier: next cell gates on s_go; hT slices are warp-private;
    // part is double-buffered; the one __syncthreads above orders part reuse.
  }
}

// ---------------- launch ----------------------------------------------------------
extern "C" void kernel_launch(void* const* d_in, const int* in_sizes, int n_in,
                              void* d_out, int out_size) {
  const float *input = 0, *hidden = 0, *w_ih = 0, *w_hh = 0, *b_ih = 0, *b_hh = 0;
  for (int i = 0; i < n_in; ++i) {
    long s = in_sizes[i];
    if (s == (long)BB * TT * HH) {
      input = (const float*)d_in[i];
    } else if (s == BB * HH && !hidden) {
      hidden = (const float*)d_in[i];
    } else if (s == 3 * HH * HH) {
      if (!w_ih) w_ih = (const float*)d_in[i]; else w_hh = (const float*)d_in[i];
    } else if (s == 3 * HH) {
      if (!b_ih) b_ih = (const float*)d_in[i]; else b_hh = (const float*)d_in[i];
    }
  }
  static int smem_set = 0;
  const int smem_bytes = (8192 + 6400 + 6400 + 16) * (int)sizeof(float);
  if (!smem_set) {
    cudaFuncSetAttribute(scan_kernel, cudaFuncAttributeMaxDynamicSharedMemorySize,
                         smem_bytes);
    smem_set = 1;
  }
  zero_ctr_kernel<<<1, 1>>>();
  gi_kernel<<<dim3(TT, 6), 256>>>(input, w_ih, b_ih);
  scan_kernel<<<NCTA, 256, smem_bytes>>>(hidden, w_hh, b_hh, (float*)d_out);
}